// round 9
// baseline (speedup 1.0000x reference)
#include <cuda_runtime.h>
#include <cstdint>
#include <cstddef>

// ---------------------------------------------------------------------------
// Problem constants
// ---------------------------------------------------------------------------
#define BATCH 8
#define HH 64
#define WW 64
#define CC 256
#define NHEADS 8
#define DPH 32
#define N_PIX (HH * WW)            // 4096
#define M_TOT (BATCH * N_PIX)      // 32768
#define N_QKV (3 * CC)             // 768
#define K_DIM CC                   // 256

// GEMM tiling: block 128x128, 4 warps (2x2), warp tile 64x64, 3-stage pipeline
#define BMT 128
#define BNT 128
#define CHK 32
#define NCHK (K_DIM / CHK)         // 8
#define NSTG 3
#define PAD 36                     // smem row stride (floats): banks (4g+t)%32 distinct
#define A_TILE (BMT * PAD)         // 4608 floats per stage
#define B_TILE (BNT * PAD)         // 4608 floats per stage
#define NTHR 128

#define M_HALF (M_TOT / 2)         // 16384 rows per half-batch

// Scratch
__device__ __align__(128) static float g_qkv[(size_t)M_TOT * N_QKV];
__device__ __align__(128) static float g_xt[(size_t)M_TOT * K_DIM];   // tf32-rounded x
__device__ __align__(128) static float g_wt[(size_t)N_QKV * K_DIM];   // tf32-rounded W

#define XT4 ((M_TOT * K_DIM) / 4)              // 2097152 float4s
#define WT4 ((N_QKV * K_DIM) / 4)              // 49152
#define PRE_BLOCKS ((XT4 + WT4) / 256)         // 8384 (exact)

// ---------------------------------------------------------------------------
// helpers
// ---------------------------------------------------------------------------
__device__ __forceinline__ uint32_t smem_u32(const void* p) {
    uint32_t a;
    asm("{ .reg .u64 t; cvta.to.shared.u64 t, %1; cvt.u32.u64 %0, t; }" : "=r"(a) : "l"(p));
    return a;
}
__device__ __forceinline__ void cp_async16(uint32_t dst, const float* src) {
    asm volatile("cp.async.cg.shared.global [%0], [%1], 16;" :: "r"(dst), "l"(src) : "memory");
}
#define CP_COMMIT() asm volatile("cp.async.commit_group;" ::: "memory")
#define CP_WAIT(n)  asm volatile("cp.async.wait_group %0;" :: "n"(n) : "memory")

__device__ __forceinline__ float to_tf32_f(float x) {
    uint32_t r;
    asm("cvt.rna.tf32.f32 %0, %1;" : "=r"(r) : "f"(x));
    return __uint_as_float(r);
}
__device__ __forceinline__ void mma_tf32(float c[4], uint32_t a0, uint32_t a1,
                                         uint32_t a2, uint32_t a3,
                                         uint32_t b0, uint32_t b1) {
    asm volatile(
        "mma.sync.aligned.m16n8k8.row.col.f32.tf32.tf32.f32 "
        "{%0,%1,%2,%3}, {%4,%5,%6,%7}, {%8,%9}, {%0,%1,%2,%3};"
        : "+f"(c[0]), "+f"(c[1]), "+f"(c[2]), "+f"(c[3])
        : "r"(a0), "r"(a1), "r"(a2), "r"(a3), "r"(b0), "r"(b1));
}

// ---------------------------------------------------------------------------
// Kernel 0: one-time RNA tf32 rounding of x and W into scratch.
// ---------------------------------------------------------------------------
__global__ __launch_bounds__(256)
void preconvert(const float* __restrict__ x, const float* __restrict__ W) {
    const int idx = blockIdx.x * 256 + threadIdx.x;
    if (idx < XT4) {
        float4 v = ((const float4*)x)[idx];
        ((float4*)g_xt)[idx] =
            make_float4(to_tf32_f(v.x), to_tf32_f(v.y), to_tf32_f(v.z), to_tf32_f(v.w));
    } else {
        const int j = idx - XT4;
        float4 v = ((const float4*)W)[j];
        ((float4*)g_wt)[j] =
            make_float4(to_tf32_f(v.x), to_tf32_f(v.y), to_tf32_f(v.z), to_tf32_f(v.w));
    }
}

// ---------------------------------------------------------------------------
// Kernel 1: qkv = xt @ wt^T via mma.sync tf32 (inputs pre-rounded).
// Block 128x128, 4 warps (2x2), warp tile 64x64, 3-stage cp.async,
// ONE __syncthreads per K-chunk:
//   wait_group(1) -> sync -> load(kc+2) -> compute(kc)
// ---------------------------------------------------------------------------
__global__ __launch_bounds__(NTHR)
void qkv_gemm_mma(int rowoff) {
    extern __shared__ float sm[];
    float* As = sm;                          // [NSTG][128][PAD]
    float* Bs = sm + NSTG * A_TILE;          // [NSTG][128][PAD]
    const uint32_t sbA = smem_u32(sm);
    const uint32_t sbB = sbA + NSTG * A_TILE * 4;

    const int tid  = threadIdx.x;
    const int lane = tid & 31;
    const int wid  = tid >> 5;               // 0..3
    const int wm   = (wid & 1) * 64;
    const int wn   = (wid >> 1) * 64;
    const int g    = lane >> 2;              // 0..7
    const int t    = lane & 3;               // 0..3
    const int bm   = rowoff + blockIdx.y * BMT;
    const int bn   = blockIdx.x * BNT;

    auto load_chunk = [&](int kc, int st) {
        const int kb = kc * CHK;
#pragma unroll
        for (int it = 0; it < 16; it++) {
            const int u = it * NTHR + tid;               // 0..2047
            if (u < 1024) {
                const int row = u >> 3, seg = u & 7;
                cp_async16(sbA + (uint32_t)(st * A_TILE + row * PAD + seg * 4) * 4,
                           g_xt + (size_t)(bm + row) * K_DIM + kb + seg * 4);
            } else {
                const int u2 = u - 1024;
                const int row = u2 >> 3, seg = u2 & 7;
                cp_async16(sbB + (uint32_t)(st * B_TILE + row * PAD + seg * 4) * 4,
                           g_wt + (size_t)(bn + row) * K_DIM + kb + seg * 4);
            }
        }
    };

    float acc[4][8][4];
#pragma unroll
    for (int i = 0; i < 4; i++)
#pragma unroll
        for (int j = 0; j < 8; j++)
#pragma unroll
            for (int r = 0; r < 4; r++) acc[i][j][r] = 0.f;

    load_chunk(0, 0); CP_COMMIT();
    load_chunk(1, 1); CP_COMMIT();

    for (int kc = 0; kc < NCHK; kc++) {
        if (kc < NCHK - 1) CP_WAIT(1);       // own group kc complete (kc+1 may pend)
        else               CP_WAIT(0);
        __syncthreads();                     // everyone's chunk kc visible; compute(kc-1) done
        if (kc + 2 < NCHK) { load_chunk(kc + 2, (kc + 2) % NSTG); CP_COMMIT(); }

        const uint32_t* Au = (const uint32_t*)(As + (kc % NSTG) * A_TILE);
        const uint32_t* Bu = (const uint32_t*)(Bs + (kc % NSTG) * B_TILE);

#pragma unroll
        for (int s = 0; s < 4; s++) {        // 4 k-steps of 8
            const int c0 = s * 8;
            uint32_t af[4][4], bf[8][2];
#pragma unroll
            for (int i = 0; i < 4; i++) {
                const int r0 = wm + i * 16;
                af[i][0] = Au[(r0 + g    ) * PAD + c0 + t    ];
                af[i][1] = Au[(r0 + g + 8) * PAD + c0 + t    ];
                af[i][2] = Au[(r0 + g    ) * PAD + c0 + t + 4];
                af[i][3] = Au[(r0 + g + 8) * PAD + c0 + t + 4];
            }
#pragma unroll
            for (int j = 0; j < 8; j++) {
                const int n0 = wn + j * 8 + g;
                bf[j][0] = Bu[n0 * PAD + c0 + t    ];
                bf[j][1] = Bu[n0 * PAD + c0 + t + 4];
            }
#pragma unroll
            for (int i = 0; i < 4; i++)
#pragma unroll
                for (int j = 0; j < 8; j++)
                    mma_tf32(acc[i][j], af[i][0], af[i][1], af[i][2], af[i][3],
                             bf[j][0], bf[j][1]);
        }
    }

    // Epilogue
#pragma unroll
    for (int i = 0; i < 4; i++) {
        const int row = bm + wm + i * 16 + g;
#pragma unroll
        for (int j = 0; j < 8; j++) {
            const int col = bn + wn + j * 8 + 2 * t;
            *(float2*)(g_qkv + (size_t)row * N_QKV + col) =
                make_float2(acc[i][j][0], acc[i][j][1]);
            *(float2*)(g_qkv + (size_t)(row + 8) * N_QKV + col) =
                make_float2(acc[i][j][2], acc[i][j][3]);
        }
    }
}

// ---------------------------------------------------------------------------
// Kernel 2: dilated local attention (half-batch per launch for L2 locality).
// Warp = 4 (b,pix,head) items, 8 lanes each, lane covers 4 channels via float4.
// OOB neighbors: score 0 in softmax (zero-pad reference semantics), v skipped.
// ---------------------------------------------------------------------------
__global__ __launch_bounds__(256) void dilate_attn(float* __restrict__ out,
                                                   int item_base) {
    const int lane = threadIdx.x & 31;
    const int wid  = threadIdx.x >> 5;
    const int sub  = lane >> 3;
    const int sl   = lane & 7;
    const int item = item_base + (blockIdx.x * 8 + wid) * 4 + sub;
    const int head = item & 7;
    const int pix  = (item >> 3) & (N_PIX - 1);
    const int b    = item >> 15;
    const int y    = pix >> 6;
    const int x    = pix & 63;

    const float4* __restrict__ q4p = (const float4*)g_qkv;
    const int rowb = (b * N_PIX + pix) * (N_QKV / 4);
    const int cb   = head * (DPH / 4) + sl;
    const float4 q4 = q4p[rowb + cb];

    float s[9];
    int   koff[9];

    if (y >= 3 && y < HH - 3 && x >= 3 && x < WW - 3) {
#pragma unroll
        for (int i = 0; i < 3; i++)
#pragma unroll
            for (int j = 0; j < 3; j++) {
                const int jj = i * 3 + j;
                koff[jj] = rowb + ((i - 1) * 3 * WW + (j - 1) * 3) * (N_QKV / 4)
                           + (CC / 4) + cb;
            }
        float4 kv[9];
#pragma unroll
        for (int jj = 0; jj < 9; jj++) kv[jj] = q4p[koff[jj]];
#pragma unroll
        for (int jj = 0; jj < 9; jj++)
            s[jj] = fmaf(q4.x, kv[jj].x, fmaf(q4.y, kv[jj].y,
                    fmaf(q4.z, kv[jj].z, q4.w * kv[jj].w)));
    } else {
#pragma unroll
        for (int i = 0; i < 3; i++)
#pragma unroll
            for (int j = 0; j < 3; j++) {
                const int jj = i * 3 + j;
                const int ny = y + (i - 1) * 3;
                const int nx = x + (j - 1) * 3;
                if (ny >= 0 && ny < HH && nx >= 0 && nx < WW) {
                    const int nb = (b * N_PIX + ny * WW + nx) * (N_QKV / 4) + (CC / 4) + cb;
                    koff[jj] = nb;
                    const float4 kv = q4p[nb];
                    s[jj] = fmaf(q4.x, kv.x, fmaf(q4.y, kv.y, fmaf(q4.z, kv.z, q4.w * kv.w)));
                } else {
                    koff[jj] = -1;
                    s[jj] = 0.f;
                }
            }
    }

#pragma unroll
    for (int off = 4; off >= 1; off >>= 1)
#pragma unroll
        for (int jj = 0; jj < 9; jj++)
            s[jj] += __shfl_xor_sync(0xffffffffu, s[jj], off);

    const float scale = 0.17677669529663687f;   // 32^-0.5
    float m = -1e30f;
#pragma unroll
    for (int jj = 0; jj < 9; jj++) { s[jj] *= scale; m = fmaxf(m, s[jj]); }
    float denom = 0.f;
    float p[9];
#pragma unroll
    for (int jj = 0; jj < 9; jj++) { p[jj] = __expf(s[jj] - m); denom += p[jj]; }
    const float inv = 1.f / denom;

    float4 o = make_float4(0.f, 0.f, 0.f, 0.f);
#pragma unroll
    for (int jj = 0; jj < 9; jj++) {
        if (koff[jj] >= 0) {
            const float4 v = q4p[koff[jj] + (CC / 4)];
            const float wj = p[jj] * inv;
            o.x = fmaf(wj, v.x, o.x);
            o.y = fmaf(wj, v.y, o.y);
            o.z = fmaf(wj, v.z, o.z);
            o.w = fmaf(wj, v.w, o.w);
        }
    }
    ((float4*)out)[(b * N_PIX + pix) * (CC / 4) + cb] = o;
}

// ---------------------------------------------------------------------------
extern "C" void kernel_launch(void* const* d_in, const int* in_sizes, int n_in,
                              void* d_out, int out_size) {
    const float* x = (const float*)d_in[0];
    const float* W = (const float*)d_in[1];
    if (n_in >= 2 && in_sizes[0] == N_QKV * K_DIM) {   // defensive order check
        x = (const float*)d_in[1];
        W = (const float*)d_in[0];
    }
    float* out = (float*)d_out;

    const int smem_bytes = NSTG * (A_TILE + B_TILE) * 4;   // 110592
    cudaFuncSetAttribute(qkv_gemm_mma, cudaFuncAttributeMaxDynamicSharedMemorySize,
                         smem_bytes);

    preconvert<<<PRE_BLOCKS, 256>>>(x, W);

    const int items_half = (BATCH / 2) * N_PIX * NHEADS;   // 131072
    dim3 ggrid(N_QKV / BNT, M_HALF / BMT);                 // (6, 128) per half
    for (int h = 0; h < 2; h++) {
        qkv_gemm_mma<<<ggrid, NTHR, smem_bytes>>>(h * M_HALF);
        dilate_attn<<<items_half / 32, 256>>>(out, h * items_half);
    }
}

// round 13
// speedup vs baseline: 1.2842x; 1.2842x over previous
#include <cuda_runtime.h>
#include <cuda_fp16.h>
#include <cstdint>
#include <cstddef>
#include <cstring>

// ---------------------------------------------------------------------------
// Problem constants
// ---------------------------------------------------------------------------
#define BATCH 8
#define HH 64
#define WW 64
#define CC 256
#define NHEADS 8
#define DPH 32
#define N_PIX (HH * WW)            // 4096
#define M_TOT (BATCH * N_PIX)      // 32768
#define N_QKV (3 * CC)             // 768
#define K_DIM CC                   // 256

// GEMM tiling: block 128x128, 8 warps (2m x 4n), warp tile 64x32, fp16 MMA k16
#define BMT 128
#define BNT 128
#define CHK 32                     // K elements per chunk
#define NCHK (K_DIM / CHK)         // 8
#define NSTG 3
#define PADU 20                    // smem row stride in uints (16 data + 4 pad)
                                   // frag banks (20g+t)%32 all distinct
#define A_TILEU (BMT * PADU)       // 2560 uints per A stage
#define B_TILEU (BNT * PADU)       // 2560 uints per B stage
#define NTHR 256

#define M_HALF (M_TOT / 2)         // 16384 rows per half-batch

// Scratch
__device__ __align__(128) static float  g_qkv[(size_t)M_TOT * N_QKV];
__device__ __align__(128) static __half g_xh[(size_t)M_TOT * K_DIM];   // fp16 x
__device__ __align__(128) static __half g_wh[(size_t)N_QKV * K_DIM];   // fp16 W

#define XT4 ((M_TOT * K_DIM) / 4)              // 2097152 float4s
#define WT4 ((N_QKV * K_DIM) / 4)              // 49152
#define PRE_BLOCKS ((XT4 + WT4) / 256)         // 8384 (exact)

// ---------------------------------------------------------------------------
// helpers
// ---------------------------------------------------------------------------
__device__ __forceinline__ uint32_t h2_bits(__half2 h) {
    uint32_t u;
    memcpy(&u, &h, 4);            // bit-cast; nvcc folds to a register move
    return u;
}
__device__ __forceinline__ uint32_t smem_u32(const void* p) {
    uint32_t a;
    asm("{ .reg .u64 t; cvta.to.shared.u64 t, %1; cvt.u32.u64 %0, t; }" : "=r"(a) : "l"(p));
    return a;
}
__device__ __forceinline__ void cp_async16(uint32_t dst, const void* src) {
    asm volatile("cp.async.cg.shared.global [%0], [%1], 16;" :: "r"(dst), "l"(src) : "memory");
}
#define CP_COMMIT() asm volatile("cp.async.commit_group;" ::: "memory")
#define CP_WAIT(n)  asm volatile("cp.async.wait_group %0;" :: "n"(n) : "memory")

__device__ __forceinline__ void mma_f16(float c[4], uint32_t a0, uint32_t a1,
                                        uint32_t a2, uint32_t a3,
                                        uint32_t b0, uint32_t b1) {
    asm volatile(
        "mma.sync.aligned.m16n8k16.row.col.f32.f16.f16.f32 "
        "{%0,%1,%2,%3}, {%4,%5,%6,%7}, {%8,%9}, {%0,%1,%2,%3};"
        : "+f"(c[0]), "+f"(c[1]), "+f"(c[2]), "+f"(c[3])
        : "r"(a0), "r"(a1), "r"(a2), "r"(a3), "r"(b0), "r"(b1));
}

// ---------------------------------------------------------------------------
// Kernel 0: one-time RN fp16 conversion of x and W into half scratch.
// ---------------------------------------------------------------------------
__global__ __launch_bounds__(256)
void preconvert(const float* __restrict__ x, const float* __restrict__ W) {
    const int idx = blockIdx.x * 256 + threadIdx.x;
    if (idx < XT4) {
        float4 v = ((const float4*)x)[idx];
        __half2 h0 = __floats2half2_rn(v.x, v.y);
        __half2 h1 = __floats2half2_rn(v.z, v.w);
        ((uint2*)g_xh)[idx] = make_uint2(h2_bits(h0), h2_bits(h1));
    } else {
        const int j = idx - XT4;
        float4 v = ((const float4*)W)[j];
        __half2 h0 = __floats2half2_rn(v.x, v.y);
        __half2 h1 = __floats2half2_rn(v.z, v.w);
        ((uint2*)g_wh)[j] = make_uint2(h2_bits(h0), h2_bits(h1));
    }
}

// ---------------------------------------------------------------------------
// Kernel 1: qkv = xh @ wh^T via mma.sync m16n8k16 fp16, fp32 accum.
// Block 128x128, 8 warps (2m x 4n), warp tile 64x32, 3-stage cp.async,
// ONE __syncthreads per K-chunk:  wait(1) -> sync -> load(kc+2) -> compute(kc)
// smem: NSTG*(A+B) = 61440 B -> 3 CTAs/SM = 24 warps/SM.
// ---------------------------------------------------------------------------
__global__ __launch_bounds__(NTHR)
void qkv_gemm_mma(int rowoff) {
    extern __shared__ uint32_t smu[];
    uint32_t* As = smu;                        // [NSTG][128][PADU]
    uint32_t* Bs = smu + NSTG * A_TILEU;       // [NSTG][128][PADU]
    const uint32_t sbA = smem_u32(smu);
    const uint32_t sbB = sbA + NSTG * A_TILEU * 4;

    const int tid  = threadIdx.x;
    const int lane = tid & 31;
    const int wid  = tid >> 5;                 // 0..7
    const int wm   = (wid & 1) * 64;           // warp m offset
    const int wn   = (wid >> 1) * 32;          // warp n offset
    const int g    = lane >> 2;                // 0..7
    const int t    = lane & 3;                 // 0..3
    const int bm   = rowoff + blockIdx.y * BMT;
    const int bn   = blockIdx.x * BNT;

    // chunk loader: A 128 rows x 64B + B 128 rows x 64B = 1024 16B units
    auto load_chunk = [&](int kc, int st) {
        const int kb = kc * CHK;               // half offset
#pragma unroll
        for (int it = 0; it < 4; it++) {
            const int u = it * NTHR + tid;     // 0..1023
            if (u < 512) {
                const int row = u >> 2, q = u & 3;        // 4 x 16B per row
                cp_async16(sbA + (uint32_t)(st * A_TILEU + row * PADU + q * 4) * 4,
                           g_xh + (size_t)(bm + row) * K_DIM + kb + q * 8);
            } else {
                const int u2 = u - 512;
                const int row = u2 >> 2, q = u2 & 3;
                cp_async16(sbB + (uint32_t)(st * B_TILEU + row * PADU + q * 4) * 4,
                           g_wh + (size_t)(bn + row) * K_DIM + kb + q * 8);
            }
        }
    };

    float acc[4][4][4];
#pragma unroll
    for (int i = 0; i < 4; i++)
#pragma unroll
        for (int j = 0; j < 4; j++)
#pragma unroll
            for (int r = 0; r < 4; r++) acc[i][j][r] = 0.f;

    load_chunk(0, 0); CP_COMMIT();
    load_chunk(1, 1); CP_COMMIT();

    for (int kc = 0; kc < NCHK; kc++) {
        if (kc < NCHK - 1) CP_WAIT(1);         // group kc done (kc+1 may pend)
        else               CP_WAIT(0);
        __syncthreads();                       // chunk kc visible; compute(kc-1) done
        if (kc + 2 < NCHK) { load_chunk(kc + 2, (kc + 2) % NSTG); CP_COMMIT(); }

        const uint32_t* Au = As + (kc % NSTG) * A_TILEU;
        const uint32_t* Bu = Bs + (kc % NSTG) * B_TILEU;

#pragma unroll
        for (int s = 0; s < 2; s++) {          // 2 k-steps of 16
            const int cu = s * 8;              // uint offset of k-step
            uint32_t af[4][4], bf[4][2];
#pragma unroll
            for (int i = 0; i < 4; i++) {
                const int r0 = wm + i * 16;
                af[i][0] = Au[(r0 + g    ) * PADU + cu + t    ];   // (g,   2t:2t+1)
                af[i][1] = Au[(r0 + g + 8) * PADU + cu + t    ];   // (g+8, 2t:2t+1)
                af[i][2] = Au[(r0 + g    ) * PADU + cu + t + 4];   // (g,   8+2t:·)
                af[i][3] = Au[(r0 + g + 8) * PADU + cu + t + 4];   // (g+8, 8+2t:·)
            }
#pragma unroll
            for (int j = 0; j < 4; j++) {
                const int n0 = wn + j * 8 + g;
                bf[j][0] = Bu[n0 * PADU + cu + t    ];             // (k=2t:·,  n=g)
                bf[j][1] = Bu[n0 * PADU + cu + t + 4];             // (k=8+2t:·,n=g)
            }
#pragma unroll
            for (int i = 0; i < 4; i++)
#pragma unroll
                for (int j = 0; j < 4; j++)
                    mma_f16(acc[i][j], af[i][0], af[i][1], af[i][2], af[i][3],
                            bf[j][0], bf[j][1]);
        }
    }

    // Epilogue: c0,c1 @(row,2t), c2,c3 @(row+8,2t)
#pragma unroll
    for (int i = 0; i < 4; i++) {
        const int row = bm + wm + i * 16 + g;
#pragma unroll
        for (int j = 0; j < 4; j++) {
            const int col = bn + wn + j * 8 + 2 * t;
            *(float2*)(g_qkv + (size_t)row * N_QKV + col) =
                make_float2(acc[i][j][0], acc[i][j][1]);
            *(float2*)(g_qkv + (size_t)(row + 8) * N_QKV + col) =
                make_float2(acc[i][j][2], acc[i][j][3]);
        }
    }
}

// ---------------------------------------------------------------------------
// Kernel 2: dilated local attention (half-batch per launch for L2 locality).
// Warp = 4 (b,pix,head) items, 8 lanes each, lane covers 4 channels via float4.
// OOB neighbors: score 0 in softmax (zero-pad reference semantics), v skipped.
// ---------------------------------------------------------------------------
__global__ __launch_bounds__(256) void dilate_attn(float* __restrict__ out,
                                                   int item_base) {
    const int lane = threadIdx.x & 31;
    const int wid  = threadIdx.x >> 5;
    const int sub  = lane >> 3;
    const int sl   = lane & 7;
    const int item = item_base + (blockIdx.x * 8 + wid) * 4 + sub;
    const int head = item & 7;
    const int pix  = (item >> 3) & (N_PIX - 1);
    const int b    = item >> 15;
    const int y    = pix >> 6;
    const int x    = pix & 63;

    const float4* __restrict__ q4p = (const float4*)g_qkv;
    const int rowb = (b * N_PIX + pix) * (N_QKV / 4);
    const int cb   = head * (DPH / 4) + sl;
    const float4 q4 = q4p[rowb + cb];

    float s[9];
    int   koff[9];

    if (y >= 3 && y < HH - 3 && x >= 3 && x < WW - 3) {
#pragma unroll
        for (int i = 0; i < 3; i++)
#pragma unroll
            for (int j = 0; j < 3; j++) {
                const int jj = i * 3 + j;
                koff[jj] = rowb + ((i - 1) * 3 * WW + (j - 1) * 3) * (N_QKV / 4)
                           + (CC / 4) + cb;
            }
        float4 kv[9];
#pragma unroll
        for (int jj = 0; jj < 9; jj++) kv[jj] = q4p[koff[jj]];
#pragma unroll
        for (int jj = 0; jj < 9; jj++)
            s[jj] = fmaf(q4.x, kv[jj].x, fmaf(q4.y, kv[jj].y,
                    fmaf(q4.z, kv[jj].z, q4.w * kv[jj].w)));
    } else {
#pragma unroll
        for (int i = 0; i < 3; i++)
#pragma unroll
            for (int j = 0; j < 3; j++) {
                const int jj = i * 3 + j;
                const int ny = y + (i - 1) * 3;
                const int nx = x + (j - 1) * 3;
                if (ny >= 0 && ny < HH && nx >= 0 && nx < WW) {
                    const int nb = (b * N_PIX + ny * WW + nx) * (N_QKV / 4) + (CC / 4) + cb;
                    koff[jj] = nb;
                    const float4 kv = q4p[nb];
                    s[jj] = fmaf(q4.x, kv.x, fmaf(q4.y, kv.y, fmaf(q4.z, kv.z, q4.w * kv.w)));
                } else {
                    koff[jj] = -1;
                    s[jj] = 0.f;
                }
            }
    }

#pragma unroll
    for (int off = 4; off >= 1; off >>= 1)
#pragma unroll
        for (int jj = 0; jj < 9; jj++)
            s[jj] += __shfl_xor_sync(0xffffffffu, s[jj], off);

    const float scale = 0.17677669529663687f;   // 32^-0.5
    float m = -1e30f;
#pragma unroll
    for (int jj = 0; jj < 9; jj++) { s[jj] *= scale; m = fmaxf(m, s[jj]); }
    float denom = 0.f;
    float p[9];
#pragma unroll
    for (int jj = 0; jj < 9; jj++) { p[jj] = __expf(s[jj] - m); denom += p[jj]; }
    const float inv = 1.f / denom;

    float4 o = make_float4(0.f, 0.f, 0.f, 0.f);
#pragma unroll
    for (int jj = 0; jj < 9; jj++) {
        if (koff[jj] >= 0) {
            const float4 v = q4p[koff[jj] + (CC / 4)];
            const float wj = p[jj] * inv;
            o.x = fmaf(wj, v.x, o.x);
            o.y = fmaf(wj, v.y, o.y);
            o.z = fmaf(wj, v.z, o.z);
            o.w = fmaf(wj, v.w, o.w);
        }
    }
    ((float4*)out)[(b * N_PIX + pix) * (CC / 4) + cb] = o;
}

// ---------------------------------------------------------------------------
extern "C" void kernel_launch(void* const* d_in, const int* in_sizes, int n_in,
                              void* d_out, int out_size) {
    const float* x = (const float*)d_in[0];
    const float* W = (const float*)d_in[1];
    if (n_in >= 2 && in_sizes[0] == N_QKV * K_DIM) {   // defensive order check
        x = (const float*)d_in[1];
        W = (const float*)d_in[0];
    }
    float* out = (float*)d_out;

    const int smem_bytes = NSTG * (A_TILEU + B_TILEU) * 4;   // 61440
    cudaFuncSetAttribute(qkv_gemm_mma, cudaFuncAttributeMaxDynamicSharedMemorySize,
                         smem_bytes);

    preconvert<<<PRE_BLOCKS, 256>>>(x, W);

    const int items_half = (BATCH / 2) * N_PIX * NHEADS;   // 131072
    dim3 ggrid(N_QKV / BNT, M_HALF / BMT);                 // (6, 128) per half
    for (int h = 0; h < 2; h++) {
        qkv_gemm_mma<<<ggrid, NTHR, smem_bytes>>>(h * M_HALF);
        dilate_attn<<<items_half / 32, 256>>>(out, h * items_half);
    }
}

// round 15
// speedup vs baseline: 1.3033x; 1.0149x over previous
#include <cuda_runtime.h>
#include <cuda_fp16.h>
#include <cstdint>
#include <cstddef>
#include <cstring>

// ---------------------------------------------------------------------------
// Problem constants
// ---------------------------------------------------------------------------
#define BATCH 8
#define HH 64
#define WW 64
#define CC 256
#define NHEADS 8
#define DPH 32
#define N_PIX (HH * WW)            // 4096
#define M_TOT (BATCH * N_PIX)      // 32768
#define N_QKV (3 * CC)             // 768
#define K_DIM CC                   // 256

// GEMM tiling: block 128x128, 8 warps (2m x 4n), warp tile 64x32, fp16 MMA k16
#define BMT 128
#define BNT 128
#define CHK 32                     // K elements per chunk
#define NCHK (K_DIM / CHK)         // 8
#define NSTG 4                     // pipeline stages (depth-3 prefetch)
#define PADU 20                    // smem row stride in uints (16 data + 4 pad)
                                   // frag banks (20g+t)%32 all distinct
#define A_TILEU (BMT * PADU)       // 2560 uints per A stage
#define B_TILEU (BNT * PADU)       // 2560 uints per B stage
#define NTHR 256

#define M_HALF (M_TOT / 2)         // 16384 rows per half-batch

// Scratch
__device__ __align__(128) static float  g_qkv[(size_t)M_TOT * N_QKV];
__device__ __align__(128) static __half g_xh[(size_t)M_TOT * K_DIM];   // fp16 x
__device__ __align__(128) static __half g_wh[(size_t)N_QKV * K_DIM];   // fp16 W

#define XT4 ((M_TOT * K_DIM) / 4)              // 2097152 float4s
#define WT4 ((N_QKV * K_DIM) / 4)              // 49152
#define PRE_BLOCKS ((XT4 + WT4) / 256)         // 8384 (exact)

// ---------------------------------------------------------------------------
// helpers
// ---------------------------------------------------------------------------
__device__ __forceinline__ uint32_t h2_bits(__half2 h) {
    uint32_t u;
    memcpy(&u, &h, 4);            // bit-cast; nvcc folds to a register move
    return u;
}
__device__ __forceinline__ uint32_t smem_u32(const void* p) {
    uint32_t a;
    asm("{ .reg .u64 t; cvta.to.shared.u64 t, %1; cvt.u32.u64 %0, t; }" : "=r"(a) : "l"(p));
    return a;
}
__device__ __forceinline__ void cp_async16(uint32_t dst, const void* src) {
    asm volatile("cp.async.cg.shared.global [%0], [%1], 16;" :: "r"(dst), "l"(src) : "memory");
}
#define CP_COMMIT() asm volatile("cp.async.commit_group;" ::: "memory")
#define CP_WAIT(n)  asm volatile("cp.async.wait_group %0;" :: "n"(n) : "memory")

__device__ __forceinline__ void mma_f16(float c[4], uint32_t a0, uint32_t a1,
                                        uint32_t a2, uint32_t a3,
                                        uint32_t b0, uint32_t b1) {
    asm volatile(
        "mma.sync.aligned.m16n8k16.row.col.f32.f16.f16.f32 "
        "{%0,%1,%2,%3}, {%4,%5,%6,%7}, {%8,%9}, {%0,%1,%2,%3};"
        : "+f"(c[0]), "+f"(c[1]), "+f"(c[2]), "+f"(c[3])
        : "r"(a0), "r"(a1), "r"(a2), "r"(a3), "r"(b0), "r"(b1));
}

// ---------------------------------------------------------------------------
// Kernel 0: one-time RN fp16 conversion of x and W into half scratch.
// ---------------------------------------------------------------------------
__global__ __launch_bounds__(256)
void preconvert(const float* __restrict__ x, const float* __restrict__ W) {
    const int idx = blockIdx.x * 256 + threadIdx.x;
    if (idx < XT4) {
        float4 v = ((const float4*)x)[idx];
        __half2 h0 = __floats2half2_rn(v.x, v.y);
        __half2 h1 = __floats2half2_rn(v.z, v.w);
        ((uint2*)g_xh)[idx] = make_uint2(h2_bits(h0), h2_bits(h1));
    } else {
        const int j = idx - XT4;
        float4 v = ((const float4*)W)[j];
        __half2 h0 = __floats2half2_rn(v.x, v.y);
        __half2 h1 = __floats2half2_rn(v.z, v.w);
        ((uint2*)g_wh)[j] = make_uint2(h2_bits(h0), h2_bits(h1));
    }
}

// ---------------------------------------------------------------------------
// Kernel 1: qkv = xh @ wh^T via mma.sync m16n8k16 fp16, fp32 accum.
// Block 128x128, 8 warps (2m x 4n), warp tile 64x32, 4-stage cp.async with
// depth-3 prefetch, ONE __syncthreads per K-chunk:
//   wait(pending) -> sync -> load(kc+3) -> compute(kc)
// smem: NSTG*(A+B) = 81920 B; regs cap residency at 2 CTAs/SM regardless.
// ---------------------------------------------------------------------------
__global__ __launch_bounds__(NTHR, 2)
void qkv_gemm_mma(int rowoff) {
    extern __shared__ uint32_t smu[];
    uint32_t* As = smu;                        // [NSTG][128][PADU]
    uint32_t* Bs = smu + NSTG * A_TILEU;       // [NSTG][128][PADU]
    const uint32_t sbA = smem_u32(smu);
    const uint32_t sbB = sbA + NSTG * A_TILEU * 4;

    const int tid  = threadIdx.x;
    const int lane = tid & 31;
    const int wid  = tid >> 5;                 // 0..7
    const int wm   = (wid & 1) * 64;           // warp m offset
    const int wn   = (wid >> 1) * 32;          // warp n offset
    const int g    = lane >> 2;                // 0..7
    const int t    = lane & 3;                 // 0..3
    const int bm   = rowoff + blockIdx.y * BMT;
    const int bn   = blockIdx.x * BNT;

    // chunk loader: A 128 rows x 64B + B 128 rows x 64B = 1024 16B units
    auto load_chunk = [&](int kc, int st) {
        const int kb = kc * CHK;               // half offset
#pragma unroll
        for (int it = 0; it < 4; it++) {
            const int u = it * NTHR + tid;     // 0..1023
            if (u < 512) {
                const int row = u >> 2, q = u & 3;        // 4 x 16B per row
                cp_async16(sbA + (uint32_t)(st * A_TILEU + row * PADU + q * 4) * 4,
                           g_xh + (size_t)(bm + row) * K_DIM + kb + q * 8);
            } else {
                const int u2 = u - 512;
                const int row = u2 >> 2, q = u2 & 3;
                cp_async16(sbB + (uint32_t)(st * B_TILEU + row * PADU + q * 4) * 4,
                           g_wh + (size_t)(bn + row) * K_DIM + kb + q * 8);
            }
        }
    };

    float acc[4][4][4];
#pragma unroll
    for (int i = 0; i < 4; i++)
#pragma unroll
        for (int j = 0; j < 4; j++)
#pragma unroll
            for (int r = 0; r < 4; r++) acc[i][j][r] = 0.f;

    load_chunk(0, 0); CP_COMMIT();
    load_chunk(1, 1); CP_COMMIT();
    load_chunk(2, 2); CP_COMMIT();

    for (int kc = 0; kc < NCHK; kc++) {
        // pending groups younger than kc = min(NCHK, kc+3) - kc - 1
        if (kc < NCHK - 2)       CP_WAIT(2);   // chunk kc complete, kc+1/kc+2 pend
        else if (kc == NCHK - 2) CP_WAIT(1);   // kc complete, kc+1 pends
        else                     CP_WAIT(0);   // all complete
        __syncthreads();                       // chunk kc visible; compute(kc-1) done
        if (kc + 3 < NCHK) { load_chunk(kc + 3, (kc + 3) % NSTG); CP_COMMIT(); }

        const uint32_t* Au = As + (kc % NSTG) * A_TILEU;
        const uint32_t* Bu = Bs + (kc % NSTG) * B_TILEU;

#pragma unroll
        for (int s = 0; s < 2; s++) {          // 2 k-steps of 16
            const int cu = s * 8;              // uint offset of k-step
            uint32_t af[4][4], bf[4][2];
#pragma unroll
            for (int i = 0; i < 4; i++) {
                const int r0 = wm + i * 16;
                af[i][0] = Au[(r0 + g    ) * PADU + cu + t    ];   // (g,   2t:2t+1)
                af[i][1] = Au[(r0 + g + 8) * PADU + cu + t    ];   // (g+8, 2t:2t+1)
                af[i][2] = Au[(r0 + g    ) * PADU + cu + t + 4];   // (g,   8+2t:·)
                af[i][3] = Au[(r0 + g + 8) * PADU + cu + t + 4];   // (g+8, 8+2t:·)
            }
#pragma unroll
            for (int j = 0; j < 4; j++) {
                const int n0 = wn + j * 8 + g;
                bf[j][0] = Bu[n0 * PADU + cu + t    ];             // (k=2t:·,  n=g)
                bf[j][1] = Bu[n0 * PADU + cu + t + 4];             // (k=8+2t:·,n=g)
            }
#pragma unroll
            for (int i = 0; i < 4; i++)
#pragma unroll
                for (int j = 0; j < 4; j++)
                    mma_f16(acc[i][j], af[i][0], af[i][1], af[i][2], af[i][3],
                            bf[j][0], bf[j][1]);
        }
    }

    // Epilogue: c0,c1 @(row,2t), c2,c3 @(row+8,2t)
#pragma unroll
    for (int i = 0; i < 4; i++) {
        const int row = bm + wm + i * 16 + g;
#pragma unroll
        for (int j = 0; j < 4; j++) {
            const int col = bn + wn + j * 8 + 2 * t;
            *(float2*)(g_qkv + (size_t)row * N_QKV + col) =
                make_float2(acc[i][j][0], acc[i][j][1]);
            *(float2*)(g_qkv + (size_t)(row + 8) * N_QKV + col) =
                make_float2(acc[i][j][2], acc[i][j][3]);
        }
    }
}

// ---------------------------------------------------------------------------
// Kernel 2: dilated local attention (half-batch per launch for L2 locality).
// Warp = 4 (b,pix,head) items, 8 lanes each, lane covers 4 channels via float4.
// OOB neighbors: score 0 in softmax (zero-pad reference semantics), v skipped.
// ---------------------------------------------------------------------------
__global__ __launch_bounds__(256) void dilate_attn(float* __restrict__ out,
                                                   int item_base) {
    const int lane = threadIdx.x & 31;
    const int wid  = threadIdx.x >> 5;
    const int sub  = lane >> 3;
    const int sl   = lane & 7;
    const int item = item_base + (blockIdx.x * 8 + wid) * 4 + sub;
    const int head = item & 7;
    const int pix  = (item >> 3) & (N_PIX - 1);
    const int b    = item >> 15;
    const int y    = pix >> 6;
    const int x    = pix & 63;

    const float4* __restrict__ q4p = (const float4*)g_qkv;
    const int rowb = (b * N_PIX + pix) * (N_QKV / 4);
    const int cb   = head * (DPH / 4) + sl;
    const float4 q4 = q4p[rowb + cb];

    float s[9];
    int   koff[9];

    if (y >= 3 && y < HH - 3 && x >= 3 && x < WW - 3) {
#pragma unroll
        for (int i = 0; i < 3; i++)
#pragma unroll
            for (int j = 0; j < 3; j++) {
                const int jj = i * 3 + j;
                koff[jj] = rowb + ((i - 1) * 3 * WW + (j - 1) * 3) * (N_QKV / 4)
                           + (CC / 4) + cb;
            }
        float4 kv[9];
#pragma unroll
        for (int jj = 0; jj < 9; jj++) kv[jj] = q4p[koff[jj]];
#pragma unroll
        for (int jj = 0; jj < 9; jj++)
            s[jj] = fmaf(q4.x, kv[jj].x, fmaf(q4.y, kv[jj].y,
                    fmaf(q4.z, kv[jj].z, q4.w * kv[jj].w)));
    } else {
#pragma unroll
        for (int i = 0; i < 3; i++)
#pragma unroll
            for (int j = 0; j < 3; j++) {
                const int jj = i * 3 + j;
                const int ny = y + (i - 1) * 3;
                const int nx = x + (j - 1) * 3;
                if (ny >= 0 && ny < HH && nx >= 0 && nx < WW) {
                    const int nb = (b * N_PIX + ny * WW + nx) * (N_QKV / 4) + (CC / 4) + cb;
                    koff[jj] = nb;
                    const float4 kv = q4p[nb];
                    s[jj] = fmaf(q4.x, kv.x, fmaf(q4.y, kv.y, fmaf(q4.z, kv.z, q4.w * kv.w)));
                } else {
                    koff[jj] = -1;
                    s[jj] = 0.f;
                }
            }
    }

#pragma unroll
    for (int off = 4; off >= 1; off >>= 1)
#pragma unroll
        for (int jj = 0; jj < 9; jj++)
            s[jj] += __shfl_xor_sync(0xffffffffu, s[jj], off);

    const float scale = 0.17677669529663687f;   // 32^-0.5
    float m = -1e30f;
#pragma unroll
    for (int jj = 0; jj < 9; jj++) { s[jj] *= scale; m = fmaxf(m, s[jj]); }
    float denom = 0.f;
    float p[9];
#pragma unroll
    for (int jj = 0; jj < 9; jj++) { p[jj] = __expf(s[jj] - m); denom += p[jj]; }
    const float inv = 1.f / denom;

    float4 o = make_float4(0.f, 0.f, 0.f, 0.f);
#pragma unroll
    for (int jj = 0; jj < 9; jj++) {
        if (koff[jj] >= 0) {
            const float4 v = q4p[koff[jj] + (CC / 4)];
            const float wj = p[jj] * inv;
            o.x = fmaf(wj, v.x, o.x);
            o.y = fmaf(wj, v.y, o.y);
            o.z = fmaf(wj, v.z, o.z);
            o.w = fmaf(wj, v.w, o.w);
        }
    }
    ((float4*)out)[(b * N_PIX + pix) * (CC / 4) + cb] = o;
}

// ---------------------------------------------------------------------------
extern "C" void kernel_launch(void* const* d_in, const int* in_sizes, int n_in,
                              void* d_out, int out_size) {
    const float* x = (const float*)d_in[0];
    const float* W = (const float*)d_in[1];
    if (n_in >= 2 && in_sizes[0] == N_QKV * K_DIM) {   // defensive order check
        x = (const float*)d_in[1];
        W = (const float*)d_in[0];
    }
    float* out = (float*)d_out;

    const int smem_bytes = NSTG * (A_TILEU + B_TILEU) * 4;   // 81920
    cudaFuncSetAttribute(qkv_gemm_mma, cudaFuncAttributeMaxDynamicSharedMemorySize,
                         smem_bytes);

    preconvert<<<PRE_BLOCKS, 256>>>(x, W);

    const int items_half = (BATCH / 2) * N_PIX * NHEADS;   // 131072
    dim3 ggrid(N_QKV / BNT, M_HALF / BMT);                 // (6, 128) per half
    for (int h = 0; h < 2; h++) {
        qkv_gemm_mma<<<ggrid, NTHR, smem_bytes>>>(h * M_HALF);
        dilate_attn<<<items_half / 32, 256>>>(out, h * items_half);
    }
}

// round 17
// speedup vs baseline: 1.3949x; 1.0703x over previous
#include <cuda_runtime.h>
#include <cuda_fp16.h>
#include <cstdint>
#include <cstddef>
#include <cstring>

// ---------------------------------------------------------------------------
// Problem constants
// ---------------------------------------------------------------------------
#define BATCH 8
#define HH 64
#define WW 64
#define CC 256
#define NHEADS 8
#define DPH 32
#define N_PIX (HH * WW)            // 4096
#define M_TOT (BATCH * N_PIX)      // 32768
#define N_QKV (3 * CC)             // 768
#define K_DIM CC                   // 256

// GEMM tiling: block 128x128, 8 warps (2m x 4n), warp tile 64x32, fp16 MMA k16
#define BMT 128
#define BNT 128
#define CHK 64                     // K elements per chunk (128 B rows)
#define NCHK (K_DIM / CHK)         // 4
#define NSTG 3                     // pipeline stages (depth-2 prefetch)
#define PADU 36                    // smem row stride in uints (32 data + 4 pad)
                                   // frag banks (36g+t)%32 = (4g+t)%32 all distinct
#define A_TILEU (BMT * PADU)       // 4608 uints per A stage
#define B_TILEU (BNT * PADU)       // 4608 uints per B stage
#define NTHR 256

#define M_HALF (M_TOT / 2)         // 16384 rows per half-batch

// Scratch
__device__ __align__(128) static float  g_qkv[(size_t)M_TOT * N_QKV];
__device__ __align__(128) static __half g_xh[(size_t)M_TOT * K_DIM];   // fp16 x
__device__ __align__(128) static __half g_wh[(size_t)N_QKV * K_DIM];   // fp16 W

#define XT4 ((M_TOT * K_DIM) / 4)              // 2097152 float4s
#define WT4 ((N_QKV * K_DIM) / 4)              // 49152
#define PRE_BLOCKS ((XT4 + WT4) / 256)         // 8384 (exact)

// ---------------------------------------------------------------------------
// helpers
// ---------------------------------------------------------------------------
__device__ __forceinline__ uint32_t h2_bits(__half2 h) {
    uint32_t u;
    memcpy(&u, &h, 4);            // bit-cast; nvcc folds to a register move
    return u;
}
__device__ __forceinline__ uint32_t smem_u32(const void* p) {
    uint32_t a;
    asm("{ .reg .u64 t; cvta.to.shared.u64 t, %1; cvt.u32.u64 %0, t; }" : "=r"(a) : "l"(p));
    return a;
}
__device__ __forceinline__ void cp_async16(uint32_t dst, const void* src) {
    asm volatile("cp.async.cg.shared.global [%0], [%1], 16;" :: "r"(dst), "l"(src) : "memory");
}
#define CP_COMMIT() asm volatile("cp.async.commit_group;" ::: "memory")
#define CP_WAIT(n)  asm volatile("cp.async.wait_group %0;" :: "n"(n) : "memory")

__device__ __forceinline__ void mma_f16(float c[4], uint32_t a0, uint32_t a1,
                                        uint32_t a2, uint32_t a3,
                                        uint32_t b0, uint32_t b1) {
    asm volatile(
        "mma.sync.aligned.m16n8k16.row.col.f32.f16.f16.f32 "
        "{%0,%1,%2,%3}, {%4,%5,%6,%7}, {%8,%9}, {%0,%1,%2,%3};"
        : "+f"(c[0]), "+f"(c[1]), "+f"(c[2]), "+f"(c[3])
        : "r"(a0), "r"(a1), "r"(a2), "r"(a3), "r"(b0), "r"(b1));
}

// ---------------------------------------------------------------------------
// Kernel 0: one-time RN fp16 conversion of x and W into half scratch.
// ---------------------------------------------------------------------------
__global__ __launch_bounds__(256)
void preconvert(const float* __restrict__ x, const float* __restrict__ W) {
    const int idx = blockIdx.x * 256 + threadIdx.x;
    if (idx < XT4) {
        float4 v = ((const float4*)x)[idx];
        __half2 h0 = __floats2half2_rn(v.x, v.y);
        __half2 h1 = __floats2half2_rn(v.z, v.w);
        ((uint2*)g_xh)[idx] = make_uint2(h2_bits(h0), h2_bits(h1));
    } else {
        const int j = idx - XT4;
        float4 v = ((const float4*)W)[j];
        __half2 h0 = __floats2half2_rn(v.x, v.y);
        __half2 h1 = __floats2half2_rn(v.z, v.w);
        ((uint2*)g_wh)[j] = make_uint2(h2_bits(h0), h2_bits(h1));
    }
}

// ---------------------------------------------------------------------------
// Kernel 1: qkv = xh @ wh^T via mma.sync m16n8k16 fp16, fp32 accum.
// Block 128x128, 8 warps (2m x 4n), warp tile 64x32.
// CHK=64: 4 K-chunks, each with 4 k-steps of 16 -> only 4 sync points,
// each amortized over 64 MMAs/warp. 3-stage cp.async, depth-2 prefetch,
// ONE __syncthreads per chunk: wait -> sync -> load(kc+2) -> compute(kc).
// smem: NSTG*(A+B) = 110592 B -> 2 CTAs/SM (regs cap at 2 regardless).
// ---------------------------------------------------------------------------
__global__ __launch_bounds__(NTHR, 2)
void qkv_gemm_mma(int rowoff) {
    extern __shared__ uint32_t smu[];
    uint32_t* As = smu;                        // [NSTG][128][PADU]
    uint32_t* Bs = smu + NSTG * A_TILEU;       // [NSTG][128][PADU]
    const uint32_t sbA = smem_u32(smu);
    const uint32_t sbB = sbA + NSTG * A_TILEU * 4;

    const int tid  = threadIdx.x;
    const int lane = tid & 31;
    const int wid  = tid >> 5;                 // 0..7
    const int wm   = (wid & 1) * 64;           // warp m offset
    const int wn   = (wid >> 1) * 32;          // warp n offset
    const int g    = lane >> 2;                // 0..7
    const int t    = lane & 3;                 // 0..3
    const int bm   = rowoff + blockIdx.y * BMT;
    const int bn   = blockIdx.x * BNT;

    // chunk loader: A 128 rows x 128B + B 128 rows x 128B = 2048 16B units
    auto load_chunk = [&](int kc, int st) {
        const int kb = kc * CHK;               // half offset
#pragma unroll
        for (int it = 0; it < 8; it++) {
            const int u = it * NTHR + tid;     // 0..2047
            if (u < 1024) {
                const int row = u >> 3, q = u & 7;        // 8 x 16B per row
                cp_async16(sbA + (uint32_t)(st * A_TILEU + row * PADU + q * 4) * 4,
                           g_xh + (size_t)(bm + row) * K_DIM + kb + q * 8);
            } else {
                const int u2 = u - 1024;
                const int row = u2 >> 3, q = u2 & 7;
                cp_async16(sbB + (uint32_t)(st * B_TILEU + row * PADU + q * 4) * 4,
                           g_wh + (size_t)(bn + row) * K_DIM + kb + q * 8);
            }
        }
    };

    float acc[4][4][4];
#pragma unroll
    for (int i = 0; i < 4; i++)
#pragma unroll
        for (int j = 0; j < 4; j++)
#pragma unroll
            for (int r = 0; r < 4; r++) acc[i][j][r] = 0.f;

    load_chunk(0, 0); CP_COMMIT();
    load_chunk(1, 1); CP_COMMIT();

    for (int kc = 0; kc < NCHK; kc++) {
        if (kc < NCHK - 1) CP_WAIT(1);         // chunk kc complete, kc+1 pends
        else               CP_WAIT(0);         // all complete
        __syncthreads();                       // chunk kc visible; compute(kc-1) done
        if (kc + 2 < NCHK) { load_chunk(kc + 2, (kc + 2) % NSTG); CP_COMMIT(); }

        const uint32_t* Au = As + (kc % NSTG) * A_TILEU;
        const uint32_t* Bu = Bs + (kc % NSTG) * B_TILEU;

#pragma unroll
        for (int s = 0; s < 4; s++) {          // 4 k-steps of 16
            const int cu = s * 8;              // uint offset of k-step
            uint32_t af[4][4], bf[4][2];
#pragma unroll
            for (int i = 0; i < 4; i++) {
                const int r0 = wm + i * 16;
                af[i][0] = Au[(r0 + g    ) * PADU + cu + t    ];   // (g,   2t:2t+1)
                af[i][1] = Au[(r0 + g + 8) * PADU + cu + t    ];   // (g+8, 2t:2t+1)
                af[i][2] = Au[(r0 + g    ) * PADU + cu + t + 4];   // (g,   8+2t:·)
                af[i][3] = Au[(r0 + g + 8) * PADU + cu + t + 4];   // (g+8, 8+2t:·)
            }
#pragma unroll
            for (int j = 0; j < 4; j++) {
                const int n0 = wn + j * 8 + g;
                bf[j][0] = Bu[n0 * PADU + cu + t    ];             // (k=2t:·,  n=g)
                bf[j][1] = Bu[n0 * PADU + cu + t + 4];             // (k=8+2t:·,n=g)
            }
#pragma unroll
            for (int i = 0; i < 4; i++)
#pragma unroll
                for (int j = 0; j < 4; j++)
                    mma_f16(acc[i][j], af[i][0], af[i][1], af[i][2], af[i][3],
                            bf[j][0], bf[j][1]);
        }
    }

    // Epilogue: c0,c1 @(row,2t), c2,c3 @(row+8,2t)
#pragma unroll
    for (int i = 0; i < 4; i++) {
        const int row = bm + wm + i * 16 + g;
#pragma unroll
        for (int j = 0; j < 4; j++) {
            const int col = bn + wn + j * 8 + 2 * t;
            *(float2*)(g_qkv + (size_t)row * N_QKV + col) =
                make_float2(acc[i][j][0], acc[i][j][1]);
            *(float2*)(g_qkv + (size_t)(row + 8) * N_QKV + col) =
                make_float2(acc[i][j][2], acc[i][j][3]);
        }
    }
}

// ---------------------------------------------------------------------------
// Kernel 2: dilated local attention (half-batch per launch for L2 locality).
// Warp = 4 (b,pix,head) items, 8 lanes each, lane covers 4 channels via float4.
// OOB neighbors: score 0 in softmax (zero-pad reference semantics), v skipped.
// ---------------------------------------------------------------------------
__global__ __launch_bounds__(256) void dilate_attn(float* __restrict__ out,
                                                   int item_base) {
    const int lane = threadIdx.x & 31;
    const int wid  = threadIdx.x >> 5;
    const int sub  = lane >> 3;
    const int sl   = lane & 7;
    const int item = item_base + (blockIdx.x * 8 + wid) * 4 + sub;
    const int head = item & 7;
    const int pix  = (item >> 3) & (N_PIX - 1);
    const int b    = item >> 15;
    const int y    = pix >> 6;
    const int x    = pix & 63;

    const float4* __restrict__ q4p = (const float4*)g_qkv;
    const int rowb = (b * N_PIX + pix) * (N_QKV / 4);
    const int cb   = head * (DPH / 4) + sl;
    const float4 q4 = q4p[rowb + cb];

    float s[9];
    int   koff[9];

    if (y >= 3 && y < HH - 3 && x >= 3 && x < WW - 3) {
#pragma unroll
        for (int i = 0; i < 3; i++)
#pragma unroll
            for (int j = 0; j < 3; j++) {
                const int jj = i * 3 + j;
                koff[jj] = rowb + ((i - 1) * 3 * WW + (j - 1) * 3) * (N_QKV / 4)
                           + (CC / 4) + cb;
            }
        float4 kv[9];
#pragma unroll
        for (int jj = 0; jj < 9; jj++) kv[jj] = q4p[koff[jj]];
#pragma unroll
        for (int jj = 0; jj < 9; jj++)
            s[jj] = fmaf(q4.x, kv[jj].x, fmaf(q4.y, kv[jj].y,
                    fmaf(q4.z, kv[jj].z, q4.w * kv[jj].w)));
    } else {
#pragma unroll
        for (int i = 0; i < 3; i++)
#pragma unroll
            for (int j = 0; j < 3; j++) {
                const int jj = i * 3 + j;
                const int ny = y + (i - 1) * 3;
                const int nx = x + (j - 1) * 3;
                if (ny >= 0 && ny < HH && nx >= 0 && nx < WW) {
                    const int nb = (b * N_PIX + ny * WW + nx) * (N_QKV / 4) + (CC / 4) + cb;
                    koff[jj] = nb;
                    const float4 kv = q4p[nb];
                    s[jj] = fmaf(q4.x, kv.x, fmaf(q4.y, kv.y, fmaf(q4.z, kv.z, q4.w * kv.w)));
                } else {
                    koff[jj] = -1;
                    s[jj] = 0.f;
                }
            }
    }

#pragma unroll
    for (int off = 4; off >= 1; off >>= 1)
#pragma unroll
        for (int jj = 0; jj < 9; jj++)
            s[jj] += __shfl_xor_sync(0xffffffffu, s[jj], off);

    const float scale = 0.17677669529663687f;   // 32^-0.5
    float m = -1e30f;
#pragma unroll
    for (int jj = 0; jj < 9; jj++) { s[jj] *= scale; m = fmaxf(m, s[jj]); }
    float denom = 0.f;
    float p[9];
#pragma unroll
    for (int jj = 0; jj < 9; jj++) { p[jj] = __expf(s[jj] - m); denom += p[jj]; }
    const float inv = 1.f / denom;

    float4 o = make_float4(0.f, 0.f, 0.f, 0.f);
#pragma unroll
    for (int jj = 0; jj < 9; jj++) {
        if (koff[jj] >= 0) {
            const float4 v = q4p[koff[jj] + (CC / 4)];
            const float wj = p[jj] * inv;
            o.x = fmaf(wj, v.x, o.x);
            o.y = fmaf(wj, v.y, o.y);
            o.z = fmaf(wj, v.z, o.z);
            o.w = fmaf(wj, v.w, o.w);
        }
    }
    ((float4*)out)[(b * N_PIX + pix) * (CC / 4) + cb] = o;
}

// ---------------------------------------------------------------------------
extern "C" void kernel_launch(void* const* d_in, const int* in_sizes, int n_in,
                              void* d_out, int out_size) {
    const float* x = (const float*)d_in[0];
    const float* W = (const float*)d_in[1];
    if (n_in >= 2 && in_sizes[0] == N_QKV * K_DIM) {   // defensive order check
        x = (const float*)d_in[1];
        W = (const float*)d_in[0];
    }
    float* out = (float*)d_out;

    const int smem_bytes = NSTG * (A_TILEU + B_TILEU) * 4;   // 110592
    cudaFuncSetAttribute(qkv_gemm_mma, cudaFuncAttributeMaxDynamicSharedMemorySize,
                         smem_bytes);

    preconvert<<<PRE_BLOCKS, 256>>>(x, W);

    const int items_half = (BATCH / 2) * N_PIX * NHEADS;   // 131072
    dim3 ggrid(N_QKV / BNT, M_HALF / BMT);                 // (6, 128) per half
    for (int h = 0; h < 2; h++) {
        qkv_gemm_mma<<<ggrid, NTHR, smem_bytes>>>(h * M_HALF);
        dilate_attn<<<items_half / 32, 256>>>(out, h * items_half);
    }
}